// round 5
// baseline (speedup 1.0000x reference)
#include <cuda_runtime.h>
#include <cuda_bf16.h>
#include <math.h>
#include <cstdint>

#define SEQ 8192
#define HID 1024
#define NCHUNK 32            // = SEQ / 256 (scores CTA row-tile)

// ---------------- device scratch (static; no runtime alloc) ----------------
__device__ __nv_bfloat16 g_ehi[(size_t)SEQ * HID];
__device__ __nv_bfloat16 g_elo[(size_t)SEQ * HID];
__device__ __nv_bfloat16 g_w1hi[HID * HID], g_w1lo[HID * HID];
__device__ __nv_bfloat16 g_w2hi[HID * HID], g_w2lo[HID * HID];
__device__ __nv_bfloat16 g_qhi[(size_t)SEQ * HID], g_qlo[(size_t)SEQ * HID];
__device__ __nv_bfloat16 g_khi[(size_t)SEQ * HID], g_klo[(size_t)SEQ * HID];
__device__ float g_sc[(size_t)SEQ * SEQ];
__device__ float g_pm[NCHUNK * SEQ];
__device__ float g_ps[NCHUNK * SEQ];
__device__ float g_cm[SEQ];
__device__ float g_cz[SEQ];

// ---------------- helpers ----------------
__device__ __forceinline__ uint32_t smem_u32(const void* p) {
    uint32_t a;
    asm("{ .reg .u64 t; cvta.to.shared.u64 t, %1; cvt.u32.u64 %0, t; }" : "=r"(a) : "l"(p));
    return a;
}
#define SWZ(off) ((off) ^ (((off) >> 3) & 0x70))
#define CP_ASYNC16(dst, src) \
    asm volatile("cp.async.cg.shared.global [%0], [%1], 16;" :: "r"(dst), "l"(src) : "memory")
#define CP_COMMIT() asm volatile("cp.async.commit_group;" ::: "memory")
#define CP_WAIT(n)  asm volatile("cp.async.wait_group %0;" :: "n"(n) : "memory")

__device__ __forceinline__ void ldsm4(uint32_t& r0, uint32_t& r1, uint32_t& r2, uint32_t& r3,
                                      uint32_t addr) {
    asm volatile("ldmatrix.sync.aligned.m8n8.x4.shared.b16 {%0,%1,%2,%3}, [%4];"
                 : "=r"(r0), "=r"(r1), "=r"(r2), "=r"(r3) : "r"(addr));
}
__device__ __forceinline__ void mma_bf16(float* c, const uint32_t* a, uint32_t b0, uint32_t b1) {
    asm volatile("mma.sync.aligned.m16n8k16.row.col.f32.bf16.bf16.f32 "
                 "{%0,%1,%2,%3}, {%4,%5,%6,%7}, {%8,%9}, {%0,%1,%2,%3};"
                 : "+f"(c[0]), "+f"(c[1]), "+f"(c[2]), "+f"(c[3])
                 : "r"(a[0]), "r"(a[1]), "r"(a[2]), "r"(a[3]), "r"(b0), "r"(b1));
}

// monotonic float<->uint for atomicMax
__device__ __forceinline__ uint32_t f2key(float f) {
    uint32_t u = __float_as_uint(f);
    return (u & 0x80000000u) ? ~u : (u | 0x80000000u);
}
__device__ __forceinline__ float key2f(uint32_t k) {
    return __uint_as_float((k & 0x80000000u) ? (k ^ 0x80000000u) : ~k);
}

// ---------------- GEMM: C = A[M,K] * B[N,K]^T, bf16x3 split ----------------
// TM = CTA rows (256 or 128); CTA cols fixed 128. 256 threads = 8 warps.
// TM=256: warps 4m x 2n (warp tile 64x64). TM=128: warps 2m x 4n (64x32).
// MODE 0: fp32 C + fused column-softmax partials.  MODE 1: tanh+split.  MODE 2: split.
template <int MODE, int TM>
__global__ __launch_bounds__(256, 1)
void gemm3_mma(const __nv_bfloat16* __restrict__ Ahi, const __nv_bfloat16* __restrict__ Alo,
               const __nv_bfloat16* __restrict__ Bhi, const __nv_bfloat16* __restrict__ Blo,
               float* __restrict__ Cf, __nv_bfloat16* __restrict__ Chi,
               __nv_bfloat16* __restrict__ Clo, int Ncols, int K)
{
    constexpr int WM  = (TM == 256) ? 4 : 2;     // warps along m
    constexpr int NT2 = (TM == 256) ? 4 : 2;     // 16-col groups per warp
    constexpr uint32_t AH_OFF = 0;
    constexpr uint32_t AL_OFF = (uint32_t)TM * 128;
    constexpr uint32_t BH_OFF = (uint32_t)2 * TM * 128;
    constexpr uint32_t BL_OFF = BH_OFF + 128 * 128;
    constexpr uint32_t STAGE  = BL_OFF + 128 * 128;
    constexpr int TROWS = 2 * TM + 256;
    constexpr int CH    = TROWS / 32;            // 16B chunks per thread per stage

    extern __shared__ char smem[];
    const uint32_t sb = smem_u32(smem);
    const int tid = threadIdx.x;
    const int l = tid & 31, w = tid >> 5;
    const int wm = w % WM, wn = w / WM;
    const int m0 = blockIdx.y * TM;
    const int n0 = blockIdx.x * 128;
    const int NS = K >> 6;

    float acc[4][2 * NT2][4];
#pragma unroll
    for (int a = 0; a < 4; a++)
#pragma unroll
        for (int b = 0; b < 2 * NT2; b++)
#pragma unroll
            for (int c = 0; c < 4; c++) acc[a][b][c] = 0.f;

    auto issue = [&](int s) {
        const int k0 = s << 6;
        const uint32_t st = sb + (uint32_t)(s & 1) * STAGE;
#pragma unroll
        for (int i = 0; i < CH; ++i) {
            const int cid = tid + i * 256;
            const int row = cid >> 3, ch = cid & 7;
            const __nv_bfloat16* g;
            uint32_t off;
            int r;
            if (row < TM)            { r = row;          g = Ahi + (size_t)(m0 + r) * K; off = AH_OFF; }
            else if (row < 2 * TM)   { r = row - TM;     g = Alo + (size_t)(m0 + r) * K; off = AL_OFF; }
            else if (row < 2 * TM + 128) { r = row - 2 * TM; g = Bhi + (size_t)(n0 + r) * K; off = BH_OFF; }
            else                     { r = row - 2 * TM - 128; g = Blo + (size_t)(n0 + r) * K; off = BL_OFF; }
            CP_ASYNC16(st + off + SWZ(r * 128 + ch * 16), g + k0 + ch * 8);
        }
        CP_COMMIT();
    };

    issue(0);

    const int arow = ((l >> 3) & 1) * 8 + (l & 7);
    const int akh  = l >> 4;
    const int brow = ((l >> 4) & 1) * 8 + (l & 7);
    const int bkh  = (l >> 3) & 1;

    for (int s = 0; s < NS; ++s) {
        if (s + 1 < NS) { issue(s + 1); CP_WAIT(1); }
        else            { CP_WAIT(0); }
        __syncthreads();
        const uint32_t st = sb + (uint32_t)(s & 1) * STAGE;

#pragma unroll
        for (int kk = 0; kk < 4; ++kk) {
            const int kb = kk * 32;
            uint32_t A[4][4], Bh[NT2][4], Bl[NT2][4];
#pragma unroll
            for (int nt2 = 0; nt2 < NT2; ++nt2) {
                const uint32_t boff = SWZ((wn * 16 * NT2 + nt2 * 16 + brow) * 128 + kb + bkh * 16);
                ldsm4(Bh[nt2][0], Bh[nt2][1], Bh[nt2][2], Bh[nt2][3], st + BH_OFF + boff);
                ldsm4(Bl[nt2][0], Bl[nt2][1], Bl[nt2][2], Bl[nt2][3], st + BL_OFF + boff);
            }
#pragma unroll
            for (int mt = 0; mt < 4; ++mt) {
                const uint32_t aoff = SWZ((wm * 64 + mt * 16 + arow) * 128 + kb + akh * 16);
                ldsm4(A[mt][0], A[mt][1], A[mt][2], A[mt][3], st + AH_OFF + aoff);
            }
#pragma unroll
            for (int mt = 0; mt < 4; ++mt)
#pragma unroll
                for (int nt2 = 0; nt2 < NT2; ++nt2) {
                    mma_bf16(acc[mt][nt2 * 2 + 0], A[mt], Bh[nt2][0], Bh[nt2][1]);
                    mma_bf16(acc[mt][nt2 * 2 + 1], A[mt], Bh[nt2][2], Bh[nt2][3]);
                    mma_bf16(acc[mt][nt2 * 2 + 0], A[mt], Bl[nt2][0], Bl[nt2][1]);
                    mma_bf16(acc[mt][nt2 * 2 + 1], A[mt], Bl[nt2][2], Bl[nt2][3]);
                }
#pragma unroll
            for (int mt = 0; mt < 4; ++mt) {
                const uint32_t aoff = SWZ((wm * 64 + mt * 16 + arow) * 128 + kb + akh * 16);
                ldsm4(A[mt][0], A[mt][1], A[mt][2], A[mt][3], st + AL_OFF + aoff);
            }
#pragma unroll
            for (int mt = 0; mt < 4; ++mt)
#pragma unroll
                for (int nt2 = 0; nt2 < NT2; ++nt2) {
                    mma_bf16(acc[mt][nt2 * 2 + 0], A[mt], Bh[nt2][0], Bh[nt2][1]);
                    mma_bf16(acc[mt][nt2 * 2 + 1], A[mt], Bh[nt2][2], Bh[nt2][3]);
                }
        }
        __syncthreads();
    }

    // ---- epilogue ----
    const int cr = l >> 2, cc = 2 * (l & 3);
#pragma unroll
    for (int mt = 0; mt < 4; ++mt) {
#pragma unroll
        for (int nt = 0; nt < 2 * NT2; ++nt) {
            const int row = m0 + wm * 64 + mt * 16 + cr;
            const int col = n0 + wn * 16 * NT2 + nt * 8 + cc;
            const float* c = acc[mt][nt];
            if (MODE == 0) {
                *(float2*)(Cf + (size_t)row * Ncols + col) = make_float2(c[0], c[1]);
                *(float2*)(Cf + (size_t)(row + 8) * Ncols + col) = make_float2(c[2], c[3]);
            } else {
#pragma unroll
                for (int h = 0; h < 2; ++h) {
                    float f0 = c[2 * h + 0], f1 = c[2 * h + 1];
                    if (MODE == 1) { f0 = tanhf(f0); f1 = tanhf(f1); }
                    __nv_bfloat16 h0 = __float2bfloat16(f0);
                    __nv_bfloat16 h1 = __float2bfloat16(f1);
                    __nv_bfloat16 l0 = __float2bfloat16(f0 - __bfloat162float(h0));
                    __nv_bfloat16 l1 = __float2bfloat16(f1 - __bfloat162float(h1));
                    const size_t o = (size_t)(row + 8 * h) * Ncols + col;
                    *(__nv_bfloat162*)(Chi + o) = __halves2bfloat162(h0, h1);
                    *(__nv_bfloat162*)(Clo + o) = __halves2bfloat162(l0, l1);
                }
            }
        }
    }

    // ---- fused column-softmax partials (scores only): this CTA covers exactly
    // one 256-row chunk x 128 cols; write per-column (max, sumexp) partials. ----
    if (MODE == 0) {
        uint32_t* smax = (uint32_t*)smem;          // [128]
        float*    ssum = (float*)(smem + 512);     // [128]
        __syncthreads();
        if (tid < 128) { smax[tid] = 0u; ssum[tid] = 0.f; }
        __syncthreads();
        // local max per column, then atomicMax
#pragma unroll
        for (int nt = 0; nt < 2 * NT2; ++nt) {
            const int colb = wn * 16 * NT2 + nt * 8 + cc;
#pragma unroll
            for (int p = 0; p < 2; ++p) {          // two adjacent columns
                float m = -3.402823e38f;
#pragma unroll
                for (int mt = 0; mt < 4; ++mt) {
                    m = fmaxf(m, acc[mt][nt][p]);
                    m = fmaxf(m, acc[mt][nt][p + 2]);
                }
                atomicMax(&smax[colb + p], f2key(m));
            }
        }
        __syncthreads();
#pragma unroll
        for (int nt = 0; nt < 2 * NT2; ++nt) {
            const int colb = wn * 16 * NT2 + nt * 8 + cc;
#pragma unroll
            for (int p = 0; p < 2; ++p) {
                const float m = key2f(smax[colb + p]);
                float s = 0.f;
#pragma unroll
                for (int mt = 0; mt < 4; ++mt) {
                    s += __expf(acc[mt][nt][p] - m);
                    s += __expf(acc[mt][nt][p + 2] - m);
                }
                atomicAdd(&ssum[colb + p], s);
            }
        }
        __syncthreads();
        if (tid < 128) {
            const int gi = blockIdx.y * SEQ + n0 + tid;
            g_pm[gi] = key2f(smax[tid]);
            g_ps[gi] = ssum[tid];
        }
    }
}

// ---------------- fp32 -> bf16 hi/lo split ----------------
__global__ void split_kernel(const float* __restrict__ src, __nv_bfloat16* __restrict__ hi,
                             __nv_bfloat16* __restrict__ lo, int n4)
{
    const int t = blockIdx.x * blockDim.x + threadIdx.x;
    if (t >= n4) return;
    float4 v = ((const float4*)src)[t];
    __nv_bfloat16 h0 = __float2bfloat16(v.x), h1 = __float2bfloat16(v.y);
    __nv_bfloat16 h2 = __float2bfloat16(v.z), h3 = __float2bfloat16(v.w);
    __nv_bfloat16 l0 = __float2bfloat16(v.x - __bfloat162float(h0));
    __nv_bfloat16 l1 = __float2bfloat16(v.y - __bfloat162float(h1));
    __nv_bfloat16 l2 = __float2bfloat16(v.z - __bfloat162float(h2));
    __nv_bfloat16 l3 = __float2bfloat16(v.w - __bfloat162float(h3));
    ((__nv_bfloat162*)hi)[2 * t + 0] = __halves2bfloat162(h0, h1);
    ((__nv_bfloat162*)hi)[2 * t + 1] = __halves2bfloat162(h2, h3);
    ((__nv_bfloat162*)lo)[2 * t + 0] = __halves2bfloat162(l0, l1);
    ((__nv_bfloat162*)lo)[2 * t + 1] = __halves2bfloat162(l2, l3);
}

// ---------------- softmax merge + normalize ----------------
__global__ void softmax_col_merge()
{
    const int j = blockIdx.x * blockDim.x + threadIdx.x;
    float m = -3.402823e38f;
#pragma unroll
    for (int c = 0; c < NCHUNK; c++) m = fmaxf(m, g_pm[c * SEQ + j]);
    float z = 0.f;
#pragma unroll
    for (int c = 0; c < NCHUNK; c++) z += g_ps[c * SEQ + j] * __expf(g_pm[c * SEQ + j] - m);
    g_cm[j] = m;
    g_cz[j] = 1.0f / z;
}

__global__ void softmax_normalize(const float* __restrict__ Sc, float* __restrict__ attn)
{
    const size_t t   = (size_t)blockIdx.x * blockDim.x + threadIdx.x;
    const size_t idx = t * 4;
    const int j = (int)(idx & (SEQ - 1));
    float4 x = *(const float4*)(Sc + idx);
    float4 m = *(const float4*)(g_cm + j);
    float4 z = *(const float4*)(g_cz + j);
    float4 o;
    o.x = __expf(x.x - m.x) * z.x;
    o.y = __expf(x.y - m.y) * z.y;
    o.z = __expf(x.z - m.z) * z.z;
    o.w = __expf(x.w - m.w) * z.w;
    *(float4*)(attn + idx) = o;
}

// context = col_sum(attn) * enc_out; softmax column sums are exactly 1 -> copy.
__global__ void copy_context(const float* __restrict__ enc, float* __restrict__ ctx)
{
    const size_t t = (size_t)blockIdx.x * blockDim.x + threadIdx.x;
    ((float4*)ctx)[t] = ((const float4*)enc)[t];
}

// ============================================================================
extern "C" void kernel_launch(void* const* d_in, const int* in_sizes, int n_in,
                              void* d_out, int out_size)
{
    const float* enc = (const float*)d_in[0];
    const float* w1  = (const float*)d_in[1];
    const float* w2  = (const float*)d_in[2];
    float* out  = (float*)d_out;
    float* ctx  = out;
    float* attn = out + (size_t)SEQ * HID;

    __nv_bfloat16 *ehi, *elo, *w1hi, *w1lo, *w2hi, *w2lo, *qhi, *qlo, *khi, *klo;
    float* sc;
    cudaGetSymbolAddress((void**)&ehi,  g_ehi);
    cudaGetSymbolAddress((void**)&elo,  g_elo);
    cudaGetSymbolAddress((void**)&w1hi, g_w1hi);
    cudaGetSymbolAddress((void**)&w1lo, g_w1lo);
    cudaGetSymbolAddress((void**)&w2hi, g_w2hi);
    cudaGetSymbolAddress((void**)&w2lo, g_w2lo);
    cudaGetSymbolAddress((void**)&qhi,  g_qhi);
    cudaGetSymbolAddress((void**)&qlo,  g_qlo);
    cudaGetSymbolAddress((void**)&khi,  g_khi);
    cudaGetSymbolAddress((void**)&klo,  g_klo);
    cudaGetSymbolAddress((void**)&sc,   g_sc);

    constexpr int SMEM_256 = 2 * (2 * 256 * 128 + 2 * 128 * 128);   // 196608
    constexpr int SMEM_128 = 2 * (2 * 128 * 128 + 2 * 128 * 128);   // 131072
    cudaFuncSetAttribute(gemm3_mma<0, 256>, cudaFuncAttributeMaxDynamicSharedMemorySize, SMEM_256);
    cudaFuncSetAttribute(gemm3_mma<1, 128>, cudaFuncAttributeMaxDynamicSharedMemorySize, SMEM_128);
    cudaFuncSetAttribute(gemm3_mma<2, 128>, cudaFuncAttributeMaxDynamicSharedMemorySize, SMEM_128);

    // 1) split inputs into bf16 hi/lo
    split_kernel<<<(SEQ * HID / 4) / 256, 256>>>(enc, ehi, elo, SEQ * HID / 4);
    split_kernel<<<(HID * HID / 4) / 256, 256>>>(w1, w1hi, w1lo, HID * HID / 4);
    split_kernel<<<(HID * HID / 4) / 256, 256>>>(w2, w2hi, w2lo, HID * HID / 4);

    // 2) q = tanh(enc @ w1^T), k = enc @ w2^T  (128x128 tiles: 512 CTAs, good waves)
    gemm3_mma<1, 128><<<dim3(HID / 128, SEQ / 128), 256, SMEM_128>>>(
        ehi, elo, w1hi, w1lo, nullptr, qhi, qlo, HID, HID);
    gemm3_mma<2, 128><<<dim3(HID / 128, SEQ / 128), 256, SMEM_128>>>(
        ehi, elo, w2hi, w2lo, nullptr, khi, klo, HID, HID);

    // 3) scores = q @ k^T (fp32) + fused column-softmax partials
    gemm3_mma<0, 256><<<dim3(SEQ / 128, SEQ / 256), 256, SMEM_256>>>(
        qhi, qlo, khi, klo, sc, nullptr, nullptr, SEQ, HID);

    // 4) merge partials + normalize
    softmax_col_merge<<<SEQ / 256, 256>>>();
    softmax_normalize<<<((size_t)SEQ * SEQ / 4) / 256, 256>>>(sc, attn);

    // 5) context = enc_out
    copy_context<<<((size_t)SEQ * HID / 4) / 256, 256>>>(enc, ctx);
}

// round 6
// speedup vs baseline: 1.0434x; 1.0434x over previous
#include <cuda_runtime.h>
#include <cuda_bf16.h>
#include <math.h>
#include <cstdint>

#define SEQ 8192
#define HID 1024
#define NCHUNK 32
#define ROWS_PER_CHUNK (SEQ / NCHUNK)

// ---------------- device scratch (static; no runtime alloc) ----------------
__device__ __nv_bfloat16 g_ehi[(size_t)SEQ * HID];
__device__ __nv_bfloat16 g_elo[(size_t)SEQ * HID];
__device__ __nv_bfloat16 g_w1hi[HID * HID], g_w1lo[HID * HID];
__device__ __nv_bfloat16 g_w2hi[HID * HID], g_w2lo[HID * HID];
__device__ __nv_bfloat16 g_qhi[(size_t)SEQ * HID], g_qlo[(size_t)SEQ * HID];
__device__ __nv_bfloat16 g_khi[(size_t)SEQ * HID], g_klo[(size_t)SEQ * HID];
__device__ float g_sc[(size_t)SEQ * SEQ];
__device__ float g_pm[NCHUNK * SEQ];
__device__ float g_ps[NCHUNK * SEQ];
__device__ float g_cm[SEQ];
__device__ float g_cz[SEQ];

// ---------------- helpers ----------------
__device__ __forceinline__ uint32_t smem_u32(const void* p) {
    uint32_t a;
    asm("{ .reg .u64 t; cvta.to.shared.u64 t, %1; cvt.u32.u64 %0, t; }" : "=r"(a) : "l"(p));
    return a;
}
#define SWZ(off) ((off) ^ (((off) >> 3) & 0x70))
#define CP_ASYNC16(dst, src) \
    asm volatile("cp.async.cg.shared.global [%0], [%1], 16;" :: "r"(dst), "l"(src) : "memory")
#define CP_COMMIT() asm volatile("cp.async.commit_group;" ::: "memory")
#define CP_WAIT(n)  asm volatile("cp.async.wait_group %0;" :: "n"(n) : "memory")

__device__ __forceinline__ void ldsm4(uint32_t& r0, uint32_t& r1, uint32_t& r2, uint32_t& r3,
                                      uint32_t addr) {
    asm volatile("ldmatrix.sync.aligned.m8n8.x4.shared.b16 {%0,%1,%2,%3}, [%4];"
                 : "=r"(r0), "=r"(r1), "=r"(r2), "=r"(r3) : "r"(addr));
}
__device__ __forceinline__ void mma_bf16(float* c, const uint32_t* a, uint32_t b0, uint32_t b1) {
    asm volatile("mma.sync.aligned.m16n8k16.row.col.f32.bf16.bf16.f32 "
                 "{%0,%1,%2,%3}, {%4,%5,%6,%7}, {%8,%9}, {%0,%1,%2,%3};"
                 : "+f"(c[0]), "+f"(c[1]), "+f"(c[2]), "+f"(c[3])
                 : "r"(a[0]), "r"(a[1]), "r"(a[2]), "r"(a[3]), "r"(b0), "r"(b1));
}

// ---------------- GEMM: C = A[M,K] * B[N,K]^T, bf16x3 split ----------------
// CTA tile 256x128, K-chunk 64. 512 threads = 16 warps (4m x 4n), warp tile 64x32.
// 2-stage cp.async double buffer.
// MODE 0: fp32 C.  MODE 1: tanh + bf16 hi/lo split.  MODE 2: bf16 hi/lo split.
#define AH_OFF 0u
#define AL_OFF 32768u
#define BH_OFF 65536u
#define BL_OFF 81920u
#define STAGE  98304u
#define SMEM_TOT (2 * STAGE)   // 192 KB

template <int MODE>
__global__ __launch_bounds__(512, 1)
void gemm3_mma(const __nv_bfloat16* __restrict__ Ahi, const __nv_bfloat16* __restrict__ Alo,
               const __nv_bfloat16* __restrict__ Bhi, const __nv_bfloat16* __restrict__ Blo,
               float* __restrict__ Cf, __nv_bfloat16* __restrict__ Chi,
               __nv_bfloat16* __restrict__ Clo, int Ncols, int K)
{
    extern __shared__ char smem[];
    const uint32_t sb = smem_u32(smem);
    const int tid = threadIdx.x;
    const int l = tid & 31, w = tid >> 5;
    const int wm = w & 3, wn = w >> 2;          // 4m x 4n warp grid
    const int m0 = blockIdx.y * 256;
    const int n0 = blockIdx.x * 128;
    const int NS = K >> 6;

    float acc[4][4][4];                          // mt x nt(8col) x quad
#pragma unroll
    for (int a = 0; a < 4; a++)
#pragma unroll
        for (int b = 0; b < 4; b++)
#pragma unroll
            for (int c = 0; c < 4; c++) acc[a][b][c] = 0.f;

    // ---- async stage loader: 768 rows x 128B = 6144 x 16B chunks, 12/thread ----
    auto issue = [&](int s) {
        const int k0 = s << 6;
        const uint32_t st = sb + (uint32_t)(s & 1) * STAGE;
#pragma unroll
        for (int i = 0; i < 12; ++i) {
            const int cid = tid + i * 512;
            const int row = cid >> 3, ch = cid & 7;
            const __nv_bfloat16* g;
            uint32_t off;
            int r;
            if (row < 256)      { r = row;       g = Ahi + (size_t)(m0 + r) * K; off = AH_OFF; }
            else if (row < 512) { r = row - 256; g = Alo + (size_t)(m0 + r) * K; off = AL_OFF; }
            else if (row < 640) { r = row - 512; g = Bhi + (size_t)(n0 + r) * K; off = BH_OFF; }
            else                { r = row - 640; g = Blo + (size_t)(n0 + r) * K; off = BL_OFF; }
            CP_ASYNC16(st + off + SWZ(r * 128 + ch * 16), g + k0 + ch * 8);
        }
        CP_COMMIT();
    };

    issue(0);

    const int arow = ((l >> 3) & 1) * 8 + (l & 7);
    const int akh  = l >> 4;
    const int brow = ((l >> 4) & 1) * 8 + (l & 7);
    const int bkh  = (l >> 3) & 1;

    for (int s = 0; s < NS; ++s) {
        if (s + 1 < NS) { issue(s + 1); CP_WAIT(1); }
        else            { CP_WAIT(0); }
        __syncthreads();
        const uint32_t st = sb + (uint32_t)(s & 1) * STAGE;

#pragma unroll
        for (int kk = 0; kk < 4; ++kk) {
            const int kb = kk * 32;
            uint32_t A[4][4], Bh[2][4], Bl[2][4];
#pragma unroll
            for (int nt2 = 0; nt2 < 2; ++nt2) {
                const uint32_t boff = SWZ((wn * 32 + nt2 * 16 + brow) * 128 + kb + bkh * 16);
                ldsm4(Bh[nt2][0], Bh[nt2][1], Bh[nt2][2], Bh[nt2][3], st + BH_OFF + boff);
                ldsm4(Bl[nt2][0], Bl[nt2][1], Bl[nt2][2], Bl[nt2][3], st + BL_OFF + boff);
            }
#pragma unroll
            for (int mt = 0; mt < 4; ++mt) {
                const uint32_t aoff = SWZ((wm * 64 + mt * 16 + arow) * 128 + kb + akh * 16);
                ldsm4(A[mt][0], A[mt][1], A[mt][2], A[mt][3], st + AH_OFF + aoff);
            }
            // hi*hi + hi*lo
#pragma unroll
            for (int mt = 0; mt < 4; ++mt)
#pragma unroll
                for (int nt2 = 0; nt2 < 2; ++nt2) {
                    mma_bf16(acc[mt][nt2 * 2 + 0], A[mt], Bh[nt2][0], Bh[nt2][1]);
                    mma_bf16(acc[mt][nt2 * 2 + 1], A[mt], Bh[nt2][2], Bh[nt2][3]);
                    mma_bf16(acc[mt][nt2 * 2 + 0], A[mt], Bl[nt2][0], Bl[nt2][1]);
                    mma_bf16(acc[mt][nt2 * 2 + 1], A[mt], Bl[nt2][2], Bl[nt2][3]);
                }
            // lo*hi (reload A as lo)
#pragma unroll
            for (int mt = 0; mt < 4; ++mt) {
                const uint32_t aoff = SWZ((wm * 64 + mt * 16 + arow) * 128 + kb + akh * 16);
                ldsm4(A[mt][0], A[mt][1], A[mt][2], A[mt][3], st + AL_OFF + aoff);
            }
#pragma unroll
            for (int mt = 0; mt < 4; ++mt)
#pragma unroll
                for (int nt2 = 0; nt2 < 2; ++nt2) {
                    mma_bf16(acc[mt][nt2 * 2 + 0], A[mt], Bh[nt2][0], Bh[nt2][1]);
                    mma_bf16(acc[mt][nt2 * 2 + 1], A[mt], Bh[nt2][2], Bh[nt2][3]);
                }
        }
        __syncthreads();
    }

    // ---- epilogue ----
    const int cr = l >> 2, cc = 2 * (l & 3);
#pragma unroll
    for (int mt = 0; mt < 4; ++mt) {
#pragma unroll
        for (int nt = 0; nt < 4; ++nt) {
            const int row = m0 + wm * 64 + mt * 16 + cr;
            const int col = n0 + wn * 32 + nt * 8 + cc;
            const float* c = acc[mt][nt];
            if (MODE == 0) {
                *(float2*)(Cf + (size_t)row * Ncols + col) = make_float2(c[0], c[1]);
                *(float2*)(Cf + (size_t)(row + 8) * Ncols + col) = make_float2(c[2], c[3]);
            } else {
#pragma unroll
                for (int h = 0; h < 2; ++h) {
                    float f0 = c[2 * h + 0], f1 = c[2 * h + 1];
                    if (MODE == 1) { f0 = tanhf(f0); f1 = tanhf(f1); }
                    __nv_bfloat16 h0 = __float2bfloat16(f0);
                    __nv_bfloat16 h1 = __float2bfloat16(f1);
                    __nv_bfloat16 l0 = __float2bfloat16(f0 - __bfloat162float(h0));
                    __nv_bfloat16 l1 = __float2bfloat16(f1 - __bfloat162float(h1));
                    const size_t o = (size_t)(row + 8 * h) * Ncols + col;
                    *(__nv_bfloat162*)(Chi + o) = __halves2bfloat162(h0, h1);
                    *(__nv_bfloat162*)(Clo + o) = __halves2bfloat162(l0, l1);
                }
            }
        }
    }
}

// ---------------- fp32 -> bf16 hi/lo split ----------------
__global__ void split_kernel(const float* __restrict__ src, __nv_bfloat16* __restrict__ hi,
                             __nv_bfloat16* __restrict__ lo, int n4)
{
    const int t = blockIdx.x * blockDim.x + threadIdx.x;
    if (t >= n4) return;
    float4 v = ((const float4*)src)[t];
    __nv_bfloat16 h0 = __float2bfloat16(v.x), h1 = __float2bfloat16(v.y);
    __nv_bfloat16 h2 = __float2bfloat16(v.z), h3 = __float2bfloat16(v.w);
    __nv_bfloat16 l0 = __float2bfloat16(v.x - __bfloat162float(h0));
    __nv_bfloat16 l1 = __float2bfloat16(v.y - __bfloat162float(h1));
    __nv_bfloat16 l2 = __float2bfloat16(v.z - __bfloat162float(h2));
    __nv_bfloat16 l3 = __float2bfloat16(v.w - __bfloat162float(h3));
    ((__nv_bfloat162*)hi)[2 * t + 0] = __halves2bfloat162(h0, h1);
    ((__nv_bfloat162*)hi)[2 * t + 1] = __halves2bfloat162(h2, h3);
    ((__nv_bfloat162*)lo)[2 * t + 0] = __halves2bfloat162(l0, l1);
    ((__nv_bfloat162*)lo)[2 * t + 1] = __halves2bfloat162(l2, l3);
}

// ---------------- column softmax over axis i ----------------
__global__ void softmax_col_partial(const float* __restrict__ Sc)
{
    const int j     = blockIdx.x * blockDim.x + threadIdx.x;
    const int chunk = blockIdx.y;
    const float* p  = Sc + (size_t)chunk * ROWS_PER_CHUNK * SEQ + j;
    float m = -3.402823e38f, s = 0.f;
#pragma unroll 8
    for (int i = 0; i < ROWS_PER_CHUNK; i++) {
        float x  = p[(size_t)i * SEQ];
        float mn = fmaxf(m, x);
        s = s * __expf(m - mn) + __expf(x - mn);
        m = mn;
    }
    g_pm[chunk * SEQ + j] = m;
    g_ps[chunk * SEQ + j] = s;
}

__global__ void softmax_col_merge()
{
    const int j = blockIdx.x * blockDim.x + threadIdx.x;
    float m = -3.402823e38f;
#pragma unroll
    for (int c = 0; c < NCHUNK; c++) m = fmaxf(m, g_pm[c * SEQ + j]);
    float z = 0.f;
#pragma unroll
    for (int c = 0; c < NCHUNK; c++) z += g_ps[c * SEQ + j] * __expf(g_pm[c * SEQ + j] - m);
    g_cm[j] = m;
    g_cz[j] = 1.0f / z;
}

__global__ void softmax_normalize(const float* __restrict__ Sc, float* __restrict__ attn)
{
    const size_t t   = (size_t)blockIdx.x * blockDim.x + threadIdx.x;
    const size_t idx = t * 4;
    const int j = (int)(idx & (SEQ - 1));
    float4 x = *(const float4*)(Sc + idx);
    float4 m = *(const float4*)(g_cm + j);
    float4 z = *(const float4*)(g_cz + j);
    float4 o;
    o.x = __expf(x.x - m.x) * z.x;
    o.y = __expf(x.y - m.y) * z.y;
    o.z = __expf(x.z - m.z) * z.z;
    o.w = __expf(x.w - m.w) * z.w;
    *(float4*)(attn + idx) = o;
}

// context = col_sum(attn) * enc_out; softmax column sums are exactly 1 -> copy.
__global__ void copy_context(const float* __restrict__ enc, float* __restrict__ ctx)
{
    const size_t t = (size_t)blockIdx.x * blockDim.x + threadIdx.x;
    ((float4*)ctx)[t] = ((const float4*)enc)[t];
}

// ============================================================================
extern "C" void kernel_launch(void* const* d_in, const int* in_sizes, int n_in,
                              void* d_out, int out_size)
{
    const float* enc = (const float*)d_in[0];
    const float* w1  = (const float*)d_in[1];
    const float* w2  = (const float*)d_in[2];
    float* out  = (float*)d_out;
    float* ctx  = out;
    float* attn = out + (size_t)SEQ * HID;

    __nv_bfloat16 *ehi, *elo, *w1hi, *w1lo, *w2hi, *w2lo, *qhi, *qlo, *khi, *klo;
    float* sc;
    cudaGetSymbolAddress((void**)&ehi,  g_ehi);
    cudaGetSymbolAddress((void**)&elo,  g_elo);
    cudaGetSymbolAddress((void**)&w1hi, g_w1hi);
    cudaGetSymbolAddress((void**)&w1lo, g_w1lo);
    cudaGetSymbolAddress((void**)&w2hi, g_w2hi);
    cudaGetSymbolAddress((void**)&w2lo, g_w2lo);
    cudaGetSymbolAddress((void**)&qhi,  g_qhi);
    cudaGetSymbolAddress((void**)&qlo,  g_qlo);
    cudaGetSymbolAddress((void**)&khi,  g_khi);
    cudaGetSymbolAddress((void**)&klo,  g_klo);
    cudaGetSymbolAddress((void**)&sc,   g_sc);

    cudaFuncSetAttribute(gemm3_mma<0>, cudaFuncAttributeMaxDynamicSharedMemorySize, SMEM_TOT);
    cudaFuncSetAttribute(gemm3_mma<1>, cudaFuncAttributeMaxDynamicSharedMemorySize, SMEM_TOT);
    cudaFuncSetAttribute(gemm3_mma<2>, cudaFuncAttributeMaxDynamicSharedMemorySize, SMEM_TOT);

    // 1) split inputs into bf16 hi/lo
    split_kernel<<<(SEQ * HID / 4) / 256, 256>>>(enc, ehi, elo, SEQ * HID / 4);
    split_kernel<<<(HID * HID / 4) / 256, 256>>>(w1, w1hi, w1lo, HID * HID / 4);
    split_kernel<<<(HID * HID / 4) / 256, 256>>>(w2, w2hi, w2lo, HID * HID / 4);

    // 2) q = tanh(enc @ w1^T), k = enc @ w2^T  (bf16 hi/lo outputs)
    gemm3_mma<1><<<dim3(HID / 128, SEQ / 256), 512, SMEM_TOT>>>(
        ehi, elo, w1hi, w1lo, nullptr, qhi, qlo, HID, HID);
    gemm3_mma<2><<<dim3(HID / 128, SEQ / 256), 512, SMEM_TOT>>>(
        ehi, elo, w2hi, w2lo, nullptr, khi, klo, HID, HID);

    // 3) scores = q @ k^T (fp32 out)
    gemm3_mma<0><<<dim3(SEQ / 128, SEQ / 256), 512, SMEM_TOT>>>(
        qhi, qlo, khi, klo, sc, nullptr, nullptr, SEQ, HID);

    // 4) column softmax
    softmax_col_partial<<<dim3(SEQ / 256, NCHUNK), 256>>>(sc);
    softmax_col_merge<<<SEQ / 256, 256>>>();
    softmax_normalize<<<((size_t)SEQ * SEQ / 4) / 256, 256>>>(sc, attn);

    // 5) context = enc_out
    copy_context<<<((size_t)SEQ * HID / 4) / 256, 256>>>(enc, ctx);
}

// round 7
// speedup vs baseline: 1.0719x; 1.0274x over previous
#include <cuda_runtime.h>
#include <cuda_bf16.h>
#include <math.h>
#include <cstdint>

#define SEQ 8192
#define HID 1024
#define NCHUNK 32
#define ROWS_PER_CHUNK (SEQ / NCHUNK)

// ---------------- device scratch (static; no runtime alloc) ----------------
__device__ __nv_bfloat16 g_ehi[(size_t)SEQ * HID];
__device__ __nv_bfloat16 g_elo[(size_t)SEQ * HID];
__device__ __nv_bfloat16 g_w1hi[HID * HID], g_w1lo[HID * HID];
__device__ __nv_bfloat16 g_w2hi[HID * HID], g_w2lo[HID * HID];
__device__ __nv_bfloat16 g_qhi[(size_t)SEQ * HID], g_qlo[(size_t)SEQ * HID];
__device__ __nv_bfloat16 g_khi[(size_t)SEQ * HID], g_klo[(size_t)SEQ * HID];
__device__ float g_sc[(size_t)SEQ * SEQ];
__device__ float g_pm[NCHUNK * SEQ];
__device__ float g_ps[NCHUNK * SEQ];
__device__ float g_cm[SEQ];
__device__ float g_cz[SEQ];

// ---------------- helpers ----------------
__device__ __forceinline__ uint32_t smem_u32(const void* p) {
    uint32_t a;
    asm("{ .reg .u64 t; cvta.to.shared.u64 t, %1; cvt.u32.u64 %0, t; }" : "=r"(a) : "l"(p));
    return a;
}
#define SWZ(off) ((off) ^ (((off) >> 3) & 0x70))
#define CP_ASYNC16(dst, src) \
    asm volatile("cp.async.cg.shared.global [%0], [%1], 16;" :: "r"(dst), "l"(src) : "memory")
#define CP_COMMIT() asm volatile("cp.async.commit_group;" ::: "memory")
#define CP_WAIT(n)  asm volatile("cp.async.wait_group %0;" :: "n"(n) : "memory")

__device__ __forceinline__ void ldsm4(uint32_t& r0, uint32_t& r1, uint32_t& r2, uint32_t& r3,
                                      uint32_t addr) {
    asm volatile("ldmatrix.sync.aligned.m8n8.x4.shared.b16 {%0,%1,%2,%3}, [%4];"
                 : "=r"(r0), "=r"(r1), "=r"(r2), "=r"(r3) : "r"(addr));
}
__device__ __forceinline__ void mma_bf16(float* c, const uint32_t* a, uint32_t b0, uint32_t b1) {
    asm volatile("mma.sync.aligned.m16n8k16.row.col.f32.bf16.bf16.f32 "
                 "{%0,%1,%2,%3}, {%4,%5,%6,%7}, {%8,%9}, {%0,%1,%2,%3};"
                 : "+f"(c[0]), "+f"(c[1]), "+f"(c[2]), "+f"(c[3])
                 : "r"(a[0]), "r"(a[1]), "r"(a[2]), "r"(a[3]), "r"(b0), "r"(b1));
}

// ---------------- GEMM: C = A[M,K] * B[N,K]^T, bf16x3 split ----------------
// CTA tile 256x128, K-chunk 64. 256 threads = 8 warps (4m x 2n), warp tile 64x64.
// 2-stage cp.async double buffer. Inner loop is phase-ordered so every fp32
// accumulator is reused at distance 32 MMAs (HMMA latency fully pipelined).
// MODE 0: fp32 C.  MODE 1: tanh + bf16 hi/lo split.  MODE 2: bf16 hi/lo split.
#define AH_OFF 0u
#define AL_OFF 32768u
#define BH_OFF 65536u
#define BL_OFF 81920u
#define STAGE  98304u
#define SMEM_TOT (2 * STAGE)   // 192 KB

template <int MODE>
__global__ __launch_bounds__(256, 1)
void gemm3_mma(const __nv_bfloat16* __restrict__ Ahi, const __nv_bfloat16* __restrict__ Alo,
               const __nv_bfloat16* __restrict__ Bhi, const __nv_bfloat16* __restrict__ Blo,
               float* __restrict__ Cf, __nv_bfloat16* __restrict__ Chi,
               __nv_bfloat16* __restrict__ Clo, int Ncols, int K)
{
    extern __shared__ char smem[];
    const uint32_t sb = smem_u32(smem);
    const int tid = threadIdx.x;
    const int l = tid & 31, w = tid >> 5;
    const int wm = w & 3, wn = w >> 2;         // 4m x 2n warp grid
    const int m0 = blockIdx.y * 256;
    const int n0 = blockIdx.x * 128;
    const int NS = K >> 6;

    float acc[4][8][4];
#pragma unroll
    for (int a = 0; a < 4; a++)
#pragma unroll
        for (int b = 0; b < 8; b++)
#pragma unroll
            for (int c = 0; c < 4; c++) acc[a][b][c] = 0.f;

    // ---- async stage loader: 768 rows x 128B = 6144 x 16B chunks, 24/thread ----
    auto issue = [&](int s) {
        const int k0 = s << 6;
        const uint32_t st = sb + (uint32_t)(s & 1) * STAGE;
#pragma unroll
        for (int i = 0; i < 24; ++i) {
            const int cid = tid + i * 256;
            const int row = cid >> 3, ch = cid & 7;
            const __nv_bfloat16* g;
            uint32_t off;
            int r;
            if (row < 256)      { r = row;       g = Ahi + (size_t)(m0 + r) * K; off = AH_OFF; }
            else if (row < 512) { r = row - 256; g = Alo + (size_t)(m0 + r) * K; off = AL_OFF; }
            else if (row < 640) { r = row - 512; g = Bhi + (size_t)(n0 + r) * K; off = BH_OFF; }
            else                { r = row - 640; g = Blo + (size_t)(n0 + r) * K; off = BL_OFF; }
            CP_ASYNC16(st + off + SWZ(r * 128 + ch * 16), g + k0 + ch * 8);
        }
        CP_COMMIT();
    };

    issue(0);

    const int arow = ((l >> 3) & 1) * 8 + (l & 7);
    const int akh  = l >> 4;
    const int brow = ((l >> 4) & 1) * 8 + (l & 7);
    const int bkh  = (l >> 3) & 1;

    for (int s = 0; s < NS; ++s) {
        if (s + 1 < NS) { issue(s + 1); CP_WAIT(1); }
        else            { CP_WAIT(0); }
        __syncthreads();
        const uint32_t st = sb + (uint32_t)(s & 1) * STAGE;

#pragma unroll
        for (int kk = 0; kk < 4; ++kk) {
            const int kb = kk * 32;
            uint32_t A[4][4], Bh[4][4], Bl[4][4];
#pragma unroll
            for (int nt2 = 0; nt2 < 4; ++nt2) {
                const uint32_t boff = SWZ((wn * 64 + nt2 * 16 + brow) * 128 + kb + bkh * 16);
                ldsm4(Bh[nt2][0], Bh[nt2][1], Bh[nt2][2], Bh[nt2][3], st + BH_OFF + boff);
                ldsm4(Bl[nt2][0], Bl[nt2][1], Bl[nt2][2], Bl[nt2][3], st + BL_OFF + boff);
            }
#pragma unroll
            for (int mt = 0; mt < 4; ++mt) {
                const uint32_t aoff = SWZ((wm * 64 + mt * 16 + arow) * 128 + kb + akh * 16);
                ldsm4(A[mt][0], A[mt][1], A[mt][2], A[mt][3], st + AH_OFF + aoff);
            }
            // Phase 1: A_hi x B_hi  — 32 MMAs, 32 distinct accumulators
#pragma unroll
            for (int mt = 0; mt < 4; ++mt)
#pragma unroll
                for (int nt2 = 0; nt2 < 4; ++nt2) {
                    mma_bf16(acc[mt][nt2 * 2 + 0], A[mt], Bh[nt2][0], Bh[nt2][1]);
                    mma_bf16(acc[mt][nt2 * 2 + 1], A[mt], Bh[nt2][2], Bh[nt2][3]);
                }
            // Phase 2: A_hi x B_lo  — reuse distance 32
#pragma unroll
            for (int mt = 0; mt < 4; ++mt)
#pragma unroll
                for (int nt2 = 0; nt2 < 4; ++nt2) {
                    mma_bf16(acc[mt][nt2 * 2 + 0], A[mt], Bl[nt2][0], Bl[nt2][1]);
                    mma_bf16(acc[mt][nt2 * 2 + 1], A[mt], Bl[nt2][2], Bl[nt2][3]);
                }
            // Phase 3: A_lo x B_hi  — reload A frags as lo, reuse distance 32
#pragma unroll
            for (int mt = 0; mt < 4; ++mt) {
                const uint32_t aoff = SWZ((wm * 64 + mt * 16 + arow) * 128 + kb + akh * 16);
                ldsm4(A[mt][0], A[mt][1], A[mt][2], A[mt][3], st + AL_OFF + aoff);
            }
#pragma unroll
            for (int mt = 0; mt < 4; ++mt)
#pragma unroll
                for (int nt2 = 0; nt2 < 4; ++nt2) {
                    mma_bf16(acc[mt][nt2 * 2 + 0], A[mt], Bh[nt2][0], Bh[nt2][1]);
                    mma_bf16(acc[mt][nt2 * 2 + 1], A[mt], Bh[nt2][2], Bh[nt2][3]);
                }
        }
        __syncthreads();
    }

    // ---- epilogue ----
    const int cr = l >> 2, cc = 2 * (l & 3);
#pragma unroll
    for (int mt = 0; mt < 4; ++mt) {
#pragma unroll
        for (int nt = 0; nt < 8; ++nt) {
            const int row = m0 + wm * 64 + mt * 16 + cr;
            const int col = n0 + wn * 64 + nt * 8 + cc;
            const float* c = acc[mt][nt];
            if (MODE == 0) {
                *(float2*)(Cf + (size_t)row * Ncols + col) = make_float2(c[0], c[1]);
                *(float2*)(Cf + (size_t)(row + 8) * Ncols + col) = make_float2(c[2], c[3]);
            } else {
#pragma unroll
                for (int h = 0; h < 2; ++h) {
                    float f0 = c[2 * h + 0], f1 = c[2 * h + 1];
                    if (MODE == 1) { f0 = tanhf(f0); f1 = tanhf(f1); }
                    __nv_bfloat16 h0 = __float2bfloat16(f0);
                    __nv_bfloat16 h1 = __float2bfloat16(f1);
                    __nv_bfloat16 l0 = __float2bfloat16(f0 - __bfloat162float(h0));
                    __nv_bfloat16 l1 = __float2bfloat16(f1 - __bfloat162float(h1));
                    const size_t o = (size_t)(row + 8 * h) * Ncols + col;
                    *(__nv_bfloat162*)(Chi + o) = __halves2bfloat162(h0, h1);
                    *(__nv_bfloat162*)(Clo + o) = __halves2bfloat162(l0, l1);
                }
            }
        }
    }
}

// ---------------- fp32 -> bf16 hi/lo split ----------------
__global__ void split_kernel(const float* __restrict__ src, __nv_bfloat16* __restrict__ hi,
                             __nv_bfloat16* __restrict__ lo, int n4)
{
    const int t = blockIdx.x * blockDim.x + threadIdx.x;
    if (t >= n4) return;
    float4 v = ((const float4*)src)[t];
    __nv_bfloat16 h0 = __float2bfloat16(v.x), h1 = __float2bfloat16(v.y);
    __nv_bfloat16 h2 = __float2bfloat16(v.z), h3 = __float2bfloat16(v.w);
    __nv_bfloat16 l0 = __float2bfloat16(v.x - __bfloat162float(h0));
    __nv_bfloat16 l1 = __float2bfloat16(v.y - __bfloat162float(h1));
    __nv_bfloat16 l2 = __float2bfloat16(v.z - __bfloat162float(h2));
    __nv_bfloat16 l3 = __float2bfloat16(v.w - __bfloat162float(h3));
    ((__nv_bfloat162*)hi)[2 * t + 0] = __halves2bfloat162(h0, h1);
    ((__nv_bfloat162*)hi)[2 * t + 1] = __halves2bfloat162(h2, h3);
    ((__nv_bfloat162*)lo)[2 * t + 0] = __halves2bfloat162(l0, l1);
    ((__nv_bfloat162*)lo)[2 * t + 1] = __halves2bfloat162(l2, l3);
}

// ---------------- column softmax over axis i ----------------
__global__ void softmax_col_partial(const float* __restrict__ Sc)
{
    const int j     = blockIdx.x * blockDim.x + threadIdx.x;
    const int chunk = blockIdx.y;
    const float* p  = Sc + (size_t)chunk * ROWS_PER_CHUNK * SEQ + j;
    float m = -3.402823e38f, s = 0.f;
#pragma unroll 8
    for (int i = 0; i < ROWS_PER_CHUNK; i++) {
        float x  = p[(size_t)i * SEQ];
        float mn = fmaxf(m, x);
        s = s * __expf(m - mn) + __expf(x - mn);
        m = mn;
    }
    g_pm[chunk * SEQ + j] = m;
    g_ps[chunk * SEQ + j] = s;
}

__global__ void softmax_col_merge()
{
    const int j = blockIdx.x * blockDim.x + threadIdx.x;
    float m = -3.402823e38f;
#pragma unroll
    for (int c = 0; c < NCHUNK; c++) m = fmaxf(m, g_pm[c * SEQ + j]);
    float z = 0.f;
#pragma unroll
    for (int c = 0; c < NCHUNK; c++) z += g_ps[c * SEQ + j] * __expf(g_pm[c * SEQ + j] - m);
    g_cm[j] = m;
    g_cz[j] = 1.0f / z;
}

__global__ void softmax_normalize(const float* __restrict__ Sc, float* __restrict__ attn)
{
    const size_t t   = (size_t)blockIdx.x * blockDim.x + threadIdx.x;
    const size_t idx = t * 4;
    const int j = (int)(idx & (SEQ - 1));
    float4 x = *(const float4*)(Sc + idx);
    float4 m = *(const float4*)(g_cm + j);
    float4 z = *(const float4*)(g_cz + j);
    float4 o;
    o.x = __expf(x.x - m.x) * z.x;
    o.y = __expf(x.y - m.y) * z.y;
    o.z = __expf(x.z - m.z) * z.z;
    o.w = __expf(x.w - m.w) * z.w;
    *(float4*)(attn + idx) = o;
}

// context = col_sum(attn) * enc_out; softmax column sums are exactly 1 -> copy.
__global__ void copy_context(const float* __restrict__ enc, float* __restrict__ ctx)
{
    const size_t t = (size_t)blockIdx.x * blockDim.x + threadIdx.x;
    ((float4*)ctx)[t] = ((const float4*)enc)[t];
}

// ============================================================================
extern "C" void kernel_launch(void* const* d_in, const int* in_sizes, int n_in,
                              void* d_out, int out_size)
{
    const float* enc = (const float*)d_in[0];
    const float* w1  = (const float*)d_in[1];
    const float* w2  = (const float*)d_in[2];
    float* out  = (float*)d_out;
    float* ctx  = out;
    float* attn = out + (size_t)SEQ * HID;

    __nv_bfloat16 *ehi, *elo, *w1hi, *w1lo, *w2hi, *w2lo, *qhi, *qlo, *khi, *klo;
    float* sc;
    cudaGetSymbolAddress((void**)&ehi,  g_ehi);
    cudaGetSymbolAddress((void**)&elo,  g_elo);
    cudaGetSymbolAddress((void**)&w1hi, g_w1hi);
    cudaGetSymbolAddress((void**)&w1lo, g_w1lo);
    cudaGetSymbolAddress((void**)&w2hi, g_w2hi);
    cudaGetSymbolAddress((void**)&w2lo, g_w2lo);
    cudaGetSymbolAddress((void**)&qhi,  g_qhi);
    cudaGetSymbolAddress((void**)&qlo,  g_qlo);
    cudaGetSymbolAddress((void**)&khi,  g_khi);
    cudaGetSymbolAddress((void**)&klo,  g_klo);
    cudaGetSymbolAddress((void**)&sc,   g_sc);

    cudaFuncSetAttribute(gemm3_mma<0>, cudaFuncAttributeMaxDynamicSharedMemorySize, SMEM_TOT);
    cudaFuncSetAttribute(gemm3_mma<1>, cudaFuncAttributeMaxDynamicSharedMemorySize, SMEM_TOT);
    cudaFuncSetAttribute(gemm3_mma<2>, cudaFuncAttributeMaxDynamicSharedMemorySize, SMEM_TOT);

    // 1) split inputs into bf16 hi/lo
    split_kernel<<<(SEQ * HID / 4) / 256, 256>>>(enc, ehi, elo, SEQ * HID / 4);
    split_kernel<<<(HID * HID / 4) / 256, 256>>>(w1, w1hi, w1lo, HID * HID / 4);
    split_kernel<<<(HID * HID / 4) / 256, 256>>>(w2, w2hi, w2lo, HID * HID / 4);

    // 2) q = tanh(enc @ w1^T), k = enc @ w2^T  (bf16 hi/lo outputs)
    gemm3_mma<1><<<dim3(HID / 128, SEQ / 256), 256, SMEM_TOT>>>(
        ehi, elo, w1hi, w1lo, nullptr, qhi, qlo, HID, HID);
    gemm3_mma<2><<<dim3(HID / 128, SEQ / 256), 256, SMEM_TOT>>>(
        ehi, elo, w2hi, w2lo, nullptr, khi, klo, HID, HID);

    // 3) scores = q @ k^T (fp32 out)
    gemm3_mma<0><<<dim3(SEQ / 128, SEQ / 256), 256, SMEM_TOT>>>(
        qhi, qlo, khi, klo, sc, nullptr, nullptr, SEQ, HID);

    // 4) column softmax
    softmax_col_partial<<<dim3(SEQ / 256, NCHUNK), 256>>>(sc);
    softmax_col_merge<<<SEQ / 256, 256>>>();
    softmax_normalize<<<((size_t)SEQ * SEQ / 4) / 256, 256>>>(sc, attn);

    // 5) context = enc_out
    copy_context<<<((size_t)SEQ * HID / 4) / 256, 256>>>(enc, ctx);
}

// round 9
// speedup vs baseline: 1.0936x; 1.0202x over previous
#include <cuda_runtime.h>
#include <cuda_bf16.h>
#include <math.h>
#include <cstdint>

#define SEQ 8192
#define HID 1024
#define NCHUNK 32
#define ROWS_PER_CHUNK (SEQ / NCHUNK)

// ---------------- device scratch (static; no runtime alloc) ----------------
__device__ __nv_bfloat16 g_ehi[(size_t)SEQ * HID];
__device__ __nv_bfloat16 g_elo[(size_t)SEQ * HID];
__device__ __nv_bfloat16 g_w1hi[HID * HID], g_w1lo[HID * HID];
__device__ __nv_bfloat16 g_w2hi[HID * HID], g_w2lo[HID * HID];
__device__ __nv_bfloat16 g_qhi[(size_t)SEQ * HID], g_qlo[(size_t)SEQ * HID];
__device__ __nv_bfloat16 g_khi[(size_t)SEQ * HID], g_klo[(size_t)SEQ * HID];
__device__ float g_sc[(size_t)SEQ * SEQ];
__device__ float g_pm[NCHUNK * SEQ];
__device__ float g_ps[NCHUNK * SEQ];
__device__ float g_cm[SEQ];
__device__ float g_cz[SEQ];

// ---------------- helpers ----------------
__device__ __forceinline__ uint32_t smem_u32(const void* p) {
    uint32_t a;
    asm("{ .reg .u64 t; cvta.to.shared.u64 t, %1; cvt.u32.u64 %0, t; }" : "=r"(a) : "l"(p));
    return a;
}
#define SWZ(off) ((off) ^ (((off) >> 3) & 0x70))
#define CP_ASYNC16(dst, src) \
    asm volatile("cp.async.cg.shared.global [%0], [%1], 16;" :: "r"(dst), "l"(src) : "memory")
#define CP_COMMIT() asm volatile("cp.async.commit_group;" ::: "memory")
#define CP_WAIT(n)  asm volatile("cp.async.wait_group %0;" :: "n"(n) : "memory")

__device__ __forceinline__ void ldsm4(uint32_t& r0, uint32_t& r1, uint32_t& r2, uint32_t& r3,
                                      uint32_t addr) {
    asm volatile("ldmatrix.sync.aligned.m8n8.x4.shared.b16 {%0,%1,%2,%3}, [%4];"
                 : "=r"(r0), "=r"(r1), "=r"(r2), "=r"(r3) : "r"(addr));
}
__device__ __forceinline__ void mma_bf16(float* c, const uint32_t* a, uint32_t b0, uint32_t b1) {
    asm volatile("mma.sync.aligned.m16n8k16.row.col.f32.bf16.bf16.f32 "
                 "{%0,%1,%2,%3}, {%4,%5,%6,%7}, {%8,%9}, {%0,%1,%2,%3};"
                 : "+f"(c[0]), "+f"(c[1]), "+f"(c[2]), "+f"(c[3])
                 : "r"(a[0]), "r"(a[1]), "r"(a[2]), "r"(a[3]), "r"(b0), "r"(b1));
}

// fast accurate-enough tanh: copysign((e-1)/(e+1), x), e = exp(2*min(|x|,15)).
// err ~2^-21 rel (MUFU ex2 + approx divide), vs 1e-3 budget: negligible.
__device__ __forceinline__ float fast_tanh(float x) {
    float ax = fminf(fabsf(x), 15.f);
    float e  = __expf(2.f * ax);
    float t  = __fdividef(e - 1.f, e + 1.f);
    return copysignf(t, x);
}

// ---------------- GEMM: C = A[M,K] * B[N,K]^T, bf16x3 split ----------------
// CTA tile 256x128, K-chunk 64. 256 threads = 8 warps (4m x 2n), warp tile 64x64.
// 2-stage cp.async double buffer.
// MODE 0: fp32 C + fused column-softmax (max,sumexp) partials (shuffle+smem, no atomics).
// MODE 1: tanh + bf16 hi/lo split.  MODE 2: bf16 hi/lo split.
#define AH_OFF 0u
#define AL_OFF 32768u
#define BH_OFF 65536u
#define BL_OFF 81920u
#define STAGE  98304u
#define SMEM_TOT (2 * STAGE)   // 192 KB

template <int MODE>
__global__ __launch_bounds__(256, 1)
void gemm3_mma(const __nv_bfloat16* __restrict__ Ahi, const __nv_bfloat16* __restrict__ Alo,
               const __nv_bfloat16* __restrict__ Bhi, const __nv_bfloat16* __restrict__ Blo,
               float* __restrict__ Cf, __nv_bfloat16* __restrict__ Chi,
               __nv_bfloat16* __restrict__ Clo, int Ncols, int K)
{
    extern __shared__ char smem[];
    const uint32_t sb = smem_u32(smem);
    const int tid = threadIdx.x;
    const int l = tid & 31, w = tid >> 5;
    const int wm = w & 3, wn = w >> 2;         // 4m x 2n warp grid
    const int m0 = blockIdx.y * 256;
    const int n0 = blockIdx.x * 128;
    const int NS = K >> 6;

    float acc[4][8][4];
#pragma unroll
    for (int a = 0; a < 4; a++)
#pragma unroll
        for (int b = 0; b < 8; b++)
#pragma unroll
            for (int c = 0; c < 4; c++) acc[a][b][c] = 0.f;

    auto issue = [&](int s) {
        const int k0 = s << 6;
        const uint32_t st = sb + (uint32_t)(s & 1) * STAGE;
#pragma unroll
        for (int i = 0; i < 24; ++i) {
            const int cid = tid + i * 256;
            const int row = cid >> 3, ch = cid & 7;
            const __nv_bfloat16* g;
            uint32_t off;
            int r;
            if (row < 256)      { r = row;       g = Ahi + (size_t)(m0 + r) * K; off = AH_OFF; }
            else if (row < 512) { r = row - 256; g = Alo + (size_t)(m0 + r) * K; off = AL_OFF; }
            else if (row < 640) { r = row - 512; g = Bhi + (size_t)(n0 + r) * K; off = BH_OFF; }
            else                { r = row - 640; g = Blo + (size_t)(n0 + r) * K; off = BL_OFF; }
            CP_ASYNC16(st + off + SWZ(r * 128 + ch * 16), g + k0 + ch * 8);
        }
        CP_COMMIT();
    };

    issue(0);

    const int arow = ((l >> 3) & 1) * 8 + (l & 7);
    const int akh  = l >> 4;
    const int brow = ((l >> 4) & 1) * 8 + (l & 7);
    const int bkh  = (l >> 3) & 1;

    for (int s = 0; s < NS; ++s) {
        if (s + 1 < NS) { issue(s + 1); CP_WAIT(1); }
        else            { CP_WAIT(0); }
        __syncthreads();
        const uint32_t st = sb + (uint32_t)(s & 1) * STAGE;

#pragma unroll
        for (int kk = 0; kk < 4; ++kk) {
            const int kb = kk * 32;
            uint32_t A[4][4], Bh[4][4], Bl[4][4];
#pragma unroll
            for (int nt2 = 0; nt2 < 4; ++nt2) {
                const uint32_t boff = SWZ((wn * 64 + nt2 * 16 + brow) * 128 + kb + bkh * 16);
                ldsm4(Bh[nt2][0], Bh[nt2][1], Bh[nt2][2], Bh[nt2][3], st + BH_OFF + boff);
                ldsm4(Bl[nt2][0], Bl[nt2][1], Bl[nt2][2], Bl[nt2][3], st + BL_OFF + boff);
            }
#pragma unroll
            for (int mt = 0; mt < 4; ++mt) {
                const uint32_t aoff = SWZ((wm * 64 + mt * 16 + arow) * 128 + kb + akh * 16);
                ldsm4(A[mt][0], A[mt][1], A[mt][2], A[mt][3], st + AH_OFF + aoff);
            }
#pragma unroll
            for (int mt = 0; mt < 4; ++mt)
#pragma unroll
                for (int nt2 = 0; nt2 < 4; ++nt2) {
                    mma_bf16(acc[mt][nt2 * 2 + 0], A[mt], Bh[nt2][0], Bh[nt2][1]);
                    mma_bf16(acc[mt][nt2 * 2 + 1], A[mt], Bh[nt2][2], Bh[nt2][3]);
                }
#pragma unroll
            for (int mt = 0; mt < 4; ++mt)
#pragma unroll
                for (int nt2 = 0; nt2 < 4; ++nt2) {
                    mma_bf16(acc[mt][nt2 * 2 + 0], A[mt], Bl[nt2][0], Bl[nt2][1]);
                    mma_bf16(acc[mt][nt2 * 2 + 1], A[mt], Bl[nt2][2], Bl[nt2][3]);
                }
#pragma unroll
            for (int mt = 0; mt < 4; ++mt) {
                const uint32_t aoff = SWZ((wm * 64 + mt * 16 + arow) * 128 + kb + akh * 16);
                ldsm4(A[mt][0], A[mt][1], A[mt][2], A[mt][3], st + AL_OFF + aoff);
            }
#pragma unroll
            for (int mt = 0; mt < 4; ++mt)
#pragma unroll
                for (int nt2 = 0; nt2 < 4; ++nt2) {
                    mma_bf16(acc[mt][nt2 * 2 + 0], A[mt], Bh[nt2][0], Bh[nt2][1]);
                    mma_bf16(acc[mt][nt2 * 2 + 1], A[mt], Bh[nt2][2], Bh[nt2][3]);
                }
        }
        __syncthreads();
    }

    // ---- epilogue: store C ----
    const int cr = l >> 2, cc = 2 * (l & 3);
#pragma unroll
    for (int mt = 0; mt < 4; ++mt) {
#pragma unroll
        for (int nt = 0; nt < 8; ++nt) {
            const int row = m0 + wm * 64 + mt * 16 + cr;
            const int col = n0 + wn * 64 + nt * 8 + cc;
            const float* c = acc[mt][nt];
            if (MODE == 0) {
                *(float2*)(Cf + (size_t)row * Ncols + col) = make_float2(c[0], c[1]);
                *(float2*)(Cf + (size_t)(row + 8) * Ncols + col) = make_float2(c[2], c[3]);
            } else {
#pragma unroll
                for (int h = 0; h < 2; ++h) {
                    float f0 = c[2 * h + 0], f1 = c[2 * h + 1];
                    if (MODE == 1) { f0 = fast_tanh(f0); f1 = fast_tanh(f1); }
                    __nv_bfloat16 h0 = __float2bfloat16(f0);
                    __nv_bfloat16 h1 = __float2bfloat16(f1);
                    __nv_bfloat16 l0 = __float2bfloat16(f0 - __bfloat162float(h0));
                    __nv_bfloat16 l1 = __float2bfloat16(f1 - __bfloat162float(h1));
                    const size_t o = (size_t)(row + 8 * h) * Ncols + col;
                    *(__nv_bfloat162*)(Chi + o) = __halves2bfloat162(h0, h1);
                    *(__nv_bfloat162*)(Clo + o) = __halves2bfloat162(l0, l1);
                }
            }
        }
    }

    // ---- MODE 0: fused column-softmax partials over this CTA's 256x128 tile ----
    // Column col is held by 8 lanes (xor 4/8/16 butterfly group) x 4 m-warps.
    // No atomics: warp shuffle reduce, then 4-way smem combine. CTA exclusively
    // owns g_pm/g_ps[blockIdx.y][n0..n0+127].
    if (MODE == 0) {
        float* sred = (float*)smem;            // [4][128]
        float* scm  = (float*)(smem + 2048);   // [128]
        __syncthreads();                       // smem stages no longer needed
        // per-column max within warp
#pragma unroll
        for (int nt = 0; nt < 8; ++nt) {
#pragma unroll
            for (int p = 0; p < 2; ++p) {
                float m = acc[0][nt][p];
#pragma unroll
                for (int mt = 0; mt < 4; ++mt) {
                    m = fmaxf(m, acc[mt][nt][p]);
                    m = fmaxf(m, acc[mt][nt][p + 2]);
                }
                m = fmaxf(m, __shfl_xor_sync(0xffffffffu, m, 4));
                m = fmaxf(m, __shfl_xor_sync(0xffffffffu, m, 8));
                m = fmaxf(m, __shfl_xor_sync(0xffffffffu, m, 16));
                sred[wm * 128 + wn * 64 + nt * 8 + cc + p] = m;   // 8 lanes write same value
            }
        }
        __syncthreads();
        if (tid < 128) {
            float m = fmaxf(fmaxf(sred[tid], sred[128 + tid]),
                            fmaxf(sred[256 + tid], sred[384 + tid]));
            scm[tid] = m;
        }
        __syncthreads();
        // per-column sumexp within warp
#pragma unroll
        for (int nt = 0; nt < 8; ++nt) {
#pragma unroll
            for (int p = 0; p < 2; ++p) {
                const float m = scm[wn * 64 + nt * 8 + cc + p];
                float s = 0.f;
#pragma unroll
                for (int mt = 0; mt < 4; ++mt) {
                    s += __expf(acc[mt][nt][p] - m);
                    s += __expf(acc[mt][nt][p + 2] - m);
                }
                s += __shfl_xor_sync(0xffffffffu, s, 4);
                s += __shfl_xor_sync(0xffffffffu, s, 8);
                s += __shfl_xor_sync(0xffffffffu, s, 16);
                sred[wm * 128 + wn * 64 + nt * 8 + cc + p] = s;
            }
        }
        __syncthreads();
        if (tid < 128) {
            const int gi = blockIdx.y * SEQ + n0 + tid;
            g_pm[gi] = scm[tid];
            g_ps[gi] = sred[tid] + sred[128 + tid] + sred[256 + tid] + sred[384 + tid];
        }
    }
}

// ---------------- fp32 -> bf16 hi/lo split ----------------
__global__ void split_kernel(const float* __restrict__ src, __nv_bfloat16* __restrict__ hi,
                             __nv_bfloat16* __restrict__ lo, int n4)
{
    const int t = blockIdx.x * blockDim.x + threadIdx.x;
    if (t >= n4) return;
    float4 v = ((const float4*)src)[t];
    __nv_bfloat16 h0 = __float2bfloat16(v.x), h1 = __float2bfloat16(v.y);
    __nv_bfloat16 h2 = __float2bfloat16(v.z), h3 = __float2bfloat16(v.w);
    __nv_bfloat16 l0 = __float2bfloat16(v.x - __bfloat162float(h0));
    __nv_bfloat16 l1 = __float2bfloat16(v.y - __bfloat162float(h1));
    __nv_bfloat16 l2 = __float2bfloat16(v.z - __bfloat162float(h2));
    __nv_bfloat16 l3 = __float2bfloat16(v.w - __bfloat162float(h3));
    ((__nv_bfloat162*)hi)[2 * t + 0] = __halves2bfloat162(h0, h1);
    ((__nv_bfloat162*)hi)[2 * t + 1] = __halves2bfloat162(h2, h3);
    ((__nv_bfloat162*)lo)[2 * t + 0] = __halves2bfloat162(l0, l1);
    ((__nv_bfloat162*)lo)[2 * t + 1] = __halves2bfloat162(l2, l3);
}

// ---------------- softmax merge + normalize ----------------
__global__ void softmax_col_merge()
{
    const int j = blockIdx.x * blockDim.x + threadIdx.x;
    float m = -3.402823e38f;
#pragma unroll
    for (int c = 0; c < NCHUNK; c++) m = fmaxf(m, g_pm[c * SEQ + j]);
    float z = 0.f;
#pragma unroll
    for (int c = 0; c < NCHUNK; c++) z += g_ps[c * SEQ + j] * __expf(g_pm[c * SEQ + j] - m);
    g_cm[j] = m;
    g_cz[j] = 1.0f / z;
}

// attn[i,j] = exp(sc[i,j]-m[j]) / Z[j]; 2x float4 per thread for MLP.
__global__ void softmax_normalize(const float* __restrict__ Sc, float* __restrict__ attn)
{
    const size_t t   = (size_t)blockIdx.x * blockDim.x + threadIdx.x;
    const size_t idx = t * 8;
    const int j = (int)(idx & (SEQ - 1));
    float4 x0 = *(const float4*)(Sc + idx);
    float4 x1 = *(const float4*)(Sc + idx + 4);
    float4 m0 = *(const float4*)(g_cm + j);
    float4 m1 = *(const float4*)(g_cm + j + 4);
    float4 z0 = *(const float4*)(g_cz + j);
    float4 z1 = *(const float4*)(g_cz + j + 4);
    float4 o0, o1;
    o0.x = __expf(x0.x - m0.x) * z0.x;
    o0.y = __expf(x0.y - m0.y) * z0.y;
    o0.z = __expf(x0.z - m0.z) * z0.z;
    o0.w = __expf(x0.w - m0.w) * z0.w;
    o1.x = __expf(x1.x - m1.x) * z1.x;
    o1.y = __expf(x1.y - m1.y) * z1.y;
    o1.z = __expf(x1.z - m1.z) * z1.z;
    o1.w = __expf(x1.w - m1.w) * z1.w;
    *(float4*)(attn + idx)     = o0;
    *(float4*)(attn + idx + 4) = o1;
}

// context = col_sum(attn) * enc_out; softmax column sums are exactly 1 -> copy.
__global__ void copy_context(const float* __restrict__ enc, float* __restrict__ ctx)
{
    const size_t t = (size_t)blockIdx.x * blockDim.x + threadIdx.x;
    ((float4*)ctx)[t] = ((const float4*)enc)[t];
}

// ============================================================================
extern "C" void kernel_launch(void* const* d_in, const int* in_sizes, int n_in,
                              void* d_out, int out_size)
{
    const float* enc = (const float*)d_in[0];
    const float* w1  = (const float*)d_in[1];
    const float* w2  = (const float*)d_in[2];
    float* out  = (float*)d_out;
    float* ctx  = out;
    float* attn = out + (size_t)SEQ * HID;

    __nv_bfloat16 *ehi, *elo, *w1hi, *w1lo, *w2hi, *w2lo, *qhi, *qlo, *khi, *klo;
    float* sc;
    cudaGetSymbolAddress((void**)&ehi,  g_ehi);
    cudaGetSymbolAddress((void**)&elo,  g_elo);
    cudaGetSymbolAddress((void**)&w1hi, g_w1hi);
    cudaGetSymbolAddress((void**)&w1lo, g_w1lo);
    cudaGetSymbolAddress((void**)&w2hi, g_w2hi);
    cudaGetSymbolAddress((void**)&w2lo, g_w2lo);
    cudaGetSymbolAddress((void**)&qhi,  g_qhi);
    cudaGetSymbolAddress((void**)&qlo,  g_qlo);
    cudaGetSymbolAddress((void**)&khi,  g_khi);
    cudaGetSymbolAddress((void**)&klo,  g_klo);
    cudaGetSymbolAddress((void**)&sc,   g_sc);

    cudaFuncSetAttribute(gemm3_mma<0>, cudaFuncAttributeMaxDynamicSharedMemorySize, SMEM_TOT);
    cudaFuncSetAttribute(gemm3_mma<1>, cudaFuncAttributeMaxDynamicSharedMemorySize, SMEM_TOT);
    cudaFuncSetAttribute(gemm3_mma<2>, cudaFuncAttributeMaxDynamicSharedMemorySize, SMEM_TOT);

    // 1) split inputs into bf16 hi/lo
    split_kernel<<<(SEQ * HID / 4) / 256, 256>>>(enc, ehi, elo, SEQ * HID / 4);
    split_kernel<<<(HID * HID / 4) / 256, 256>>>(w1, w1hi, w1lo, HID * HID / 4);
    split_kernel<<<(HID * HID / 4) / 256, 256>>>(w2, w2hi, w2lo, HID * HID / 4);

    // 2) q = tanh(enc @ w1^T), k = enc @ w2^T  (bf16 hi/lo outputs)
    gemm3_mma<1><<<dim3(HID / 128, SEQ / 256), 256, SMEM_TOT>>>(
        ehi, elo, w1hi, w1lo, nullptr, qhi, qlo, HID, HID);
    gemm3_mma<2><<<dim3(HID / 128, SEQ / 256), 256, SMEM_TOT>>>(
        ehi, elo, w2hi, w2lo, nullptr, khi, klo, HID, HID);

    // 3) scores = q @ k^T (fp32) + fused column-softmax partials
    gemm3_mma<0><<<dim3(SEQ / 128, SEQ / 256), 256, SMEM_TOT>>>(
        qhi, qlo, khi, klo, sc, nullptr, nullptr, SEQ, HID);

    // 4) merge partials + normalize
    softmax_col_merge<<<SEQ / 256, 256>>>();
    softmax_normalize<<<((size_t)SEQ * SEQ / 8) / 256, 256>>>(sc, attn);

    // 5) context = enc_out
    copy_context<<<((size_t)SEQ * HID / 4) / 256, 256>>>(enc, ctx);
}

// round 10
// speedup vs baseline: 1.0969x; 1.0029x over previous
#include <cuda_runtime.h>
#include <cuda_bf16.h>
#include <math.h>
#include <cstdint>

#define SEQ 8192
#define HID 1024
#define NCHUNK 32

// ---------------- device scratch (static; no runtime alloc) ----------------
__device__ __nv_bfloat16 g_ehi[(size_t)SEQ * HID];
__device__ __nv_bfloat16 g_elo[(size_t)SEQ * HID];
__device__ __nv_bfloat16 g_wfhi[2 * HID * HID], g_wflo[2 * HID * HID];   // [w1;w2]
__device__ __nv_bfloat16 g_qhi[(size_t)SEQ * HID], g_qlo[(size_t)SEQ * HID];
__device__ __nv_bfloat16 g_khi[(size_t)SEQ * HID], g_klo[(size_t)SEQ * HID];
__device__ float g_sc[(size_t)SEQ * SEQ];
__device__ float g_pm[NCHUNK * SEQ];
__device__ float g_ps[NCHUNK * SEQ];
__device__ float g_cm[SEQ];
__device__ float g_cz[SEQ];

// ---------------- helpers ----------------
__device__ __forceinline__ uint32_t smem_u32(const void* p) {
    uint32_t a;
    asm("{ .reg .u64 t; cvta.to.shared.u64 t, %1; cvt.u32.u64 %0, t; }" : "=r"(a) : "l"(p));
    return a;
}
#define SWZ(off) ((off) ^ (((off) >> 3) & 0x70))
#define CP_ASYNC16(dst, src) \
    asm volatile("cp.async.cg.shared.global [%0], [%1], 16;" :: "r"(dst), "l"(src) : "memory")
#define CP_COMMIT() asm volatile("cp.async.commit_group;" ::: "memory")
#define CP_WAIT(n)  asm volatile("cp.async.wait_group %0;" :: "n"(n) : "memory")

__device__ __forceinline__ void ldsm4(uint32_t& r0, uint32_t& r1, uint32_t& r2, uint32_t& r3,
                                      uint32_t addr) {
    asm volatile("ldmatrix.sync.aligned.m8n8.x4.shared.b16 {%0,%1,%2,%3}, [%4];"
                 : "=r"(r0), "=r"(r1), "=r"(r2), "=r"(r3) : "r"(addr));
}
__device__ __forceinline__ void mma_bf16(float* c, const uint32_t* a, uint32_t b0, uint32_t b1) {
    asm volatile("mma.sync.aligned.m16n8k16.row.col.f32.bf16.bf16.f32 "
                 "{%0,%1,%2,%3}, {%4,%5,%6,%7}, {%8,%9}, {%0,%1,%2,%3};"
                 : "+f"(c[0]), "+f"(c[1]), "+f"(c[2]), "+f"(c[3])
                 : "r"(a[0]), "r"(a[1]), "r"(a[2]), "r"(a[3]), "r"(b0), "r"(b1));
}

// fast tanh: copysign((e-1)/(e+1), x), e = exp(2*min(|x|,15)); err ~2^-21.
__device__ __forceinline__ float fast_tanh(float x) {
    float ax = fminf(fabsf(x), 15.f);
    float e  = __expf(2.f * ax);
    float t  = __fdividef(e - 1.f, e + 1.f);
    return copysignf(t, x);
}

// ---------------- GEMM: C = A[M,K] * B[N,K]^T, bf16x3 split ----------------
// CTA tile 256x128, K-chunk 64. 256 threads = 8 warps (4m x 2n), warp tile 64x64.
// 2-stage cp.async double buffer.
// MODE 0: fp32 C + fused column-softmax (max,sumexp) partials.
// MODE 3: fused q/k producer — cols [0,HID) -> tanh+split into Qhi/Qlo,
//         cols [HID,2*HID) -> split into Khi/Klo.
#define AH_OFF 0u
#define AL_OFF 32768u
#define BH_OFF 65536u
#define BL_OFF 81920u
#define STAGE  98304u
#define SMEM_TOT (2 * STAGE)   // 192 KB

template <int MODE>
__global__ __launch_bounds__(256, 1)
void gemm3_mma(const __nv_bfloat16* __restrict__ Ahi, const __nv_bfloat16* __restrict__ Alo,
               const __nv_bfloat16* __restrict__ Bhi, const __nv_bfloat16* __restrict__ Blo,
               float* __restrict__ Cf,
               __nv_bfloat16* __restrict__ Qhi, __nv_bfloat16* __restrict__ Qlo,
               __nv_bfloat16* __restrict__ Khi, __nv_bfloat16* __restrict__ Klo,
               int Ncols, int K)
{
    extern __shared__ char smem[];
    const uint32_t sb = smem_u32(smem);
    const int tid = threadIdx.x;
    const int l = tid & 31, w = tid >> 5;
    const int wm = w & 3, wn = w >> 2;         // 4m x 2n warp grid
    const int m0 = blockIdx.y * 256;
    const int n0 = blockIdx.x * 128;
    const int NS = K >> 6;

    float acc[4][8][4];
#pragma unroll
    for (int a = 0; a < 4; a++)
#pragma unroll
        for (int b = 0; b < 8; b++)
#pragma unroll
            for (int c = 0; c < 4; c++) acc[a][b][c] = 0.f;

    auto issue = [&](int s) {
        const int k0 = s << 6;
        const uint32_t st = sb + (uint32_t)(s & 1) * STAGE;
#pragma unroll
        for (int i = 0; i < 24; ++i) {
            const int cid = tid + i * 256;
            const int row = cid >> 3, ch = cid & 7;
            const __nv_bfloat16* g;
            uint32_t off;
            int r;
            if (row < 256)      { r = row;       g = Ahi + (size_t)(m0 + r) * K; off = AH_OFF; }
            else if (row < 512) { r = row - 256; g = Alo + (size_t)(m0 + r) * K; off = AL_OFF; }
            else if (row < 640) { r = row - 512; g = Bhi + (size_t)(n0 + r) * K; off = BH_OFF; }
            else                { r = row - 640; g = Blo + (size_t)(n0 + r) * K; off = BL_OFF; }
            CP_ASYNC16(st + off + SWZ(r * 128 + ch * 16), g + k0 + ch * 8);
        }
        CP_COMMIT();
    };

    issue(0);

    const int arow = ((l >> 3) & 1) * 8 + (l & 7);
    const int akh  = l >> 4;
    const int brow = ((l >> 4) & 1) * 8 + (l & 7);
    const int bkh  = (l >> 3) & 1;

    for (int s = 0; s < NS; ++s) {
        if (s + 1 < NS) { issue(s + 1); CP_WAIT(1); }
        else            { CP_WAIT(0); }
        __syncthreads();
        const uint32_t st = sb + (uint32_t)(s & 1) * STAGE;

#pragma unroll
        for (int kk = 0; kk < 4; ++kk) {
            const int kb = kk * 32;
            uint32_t A[4][4], Bh[4][4], Bl[4][4];
#pragma unroll
            for (int nt2 = 0; nt2 < 4; ++nt2) {
                const uint32_t boff = SWZ((wn * 64 + nt2 * 16 + brow) * 128 + kb + bkh * 16);
                ldsm4(Bh[nt2][0], Bh[nt2][1], Bh[nt2][2], Bh[nt2][3], st + BH_OFF + boff);
                ldsm4(Bl[nt2][0], Bl[nt2][1], Bl[nt2][2], Bl[nt2][3], st + BL_OFF + boff);
            }
#pragma unroll
            for (int mt = 0; mt < 4; ++mt) {
                const uint32_t aoff = SWZ((wm * 64 + mt * 16 + arow) * 128 + kb + akh * 16);
                ldsm4(A[mt][0], A[mt][1], A[mt][2], A[mt][3], st + AH_OFF + aoff);
            }
#pragma unroll
            for (int mt = 0; mt < 4; ++mt)
#pragma unroll
                for (int nt2 = 0; nt2 < 4; ++nt2) {
                    mma_bf16(acc[mt][nt2 * 2 + 0], A[mt], Bh[nt2][0], Bh[nt2][1]);
                    mma_bf16(acc[mt][nt2 * 2 + 1], A[mt], Bh[nt2][2], Bh[nt2][3]);
                }
#pragma unroll
            for (int mt = 0; mt < 4; ++mt)
#pragma unroll
                for (int nt2 = 0; nt2 < 4; ++nt2) {
                    mma_bf16(acc[mt][nt2 * 2 + 0], A[mt], Bl[nt2][0], Bl[nt2][1]);
                    mma_bf16(acc[mt][nt2 * 2 + 1], A[mt], Bl[nt2][2], Bl[nt2][3]);
                }
#pragma unroll
            for (int mt = 0; mt < 4; ++mt) {
                const uint32_t aoff = SWZ((wm * 64 + mt * 16 + arow) * 128 + kb + akh * 16);
                ldsm4(A[mt][0], A[mt][1], A[mt][2], A[mt][3], st + AL_OFF + aoff);
            }
#pragma unroll
            for (int mt = 0; mt < 4; ++mt)
#pragma unroll
                for (int nt2 = 0; nt2 < 4; ++nt2) {
                    mma_bf16(acc[mt][nt2 * 2 + 0], A[mt], Bh[nt2][0], Bh[nt2][1]);
                    mma_bf16(acc[mt][nt2 * 2 + 1], A[mt], Bh[nt2][2], Bh[nt2][3]);
                }
        }
        __syncthreads();
    }

    // ---- epilogue: store C ----
    const int cr = l >> 2, cc = 2 * (l & 3);
    if (MODE == 0) {
#pragma unroll
        for (int mt = 0; mt < 4; ++mt)
#pragma unroll
            for (int nt = 0; nt < 8; ++nt) {
                const int row = m0 + wm * 64 + mt * 16 + cr;
                const int col = n0 + wn * 64 + nt * 8 + cc;
                const float* c = acc[mt][nt];
                *(float2*)(Cf + (size_t)row * Ncols + col) = make_float2(c[0], c[1]);
                *(float2*)(Cf + (size_t)(row + 8) * Ncols + col) = make_float2(c[2], c[3]);
            }
    } else {
        const bool is_k = (n0 >= HID);
        __nv_bfloat16* Ho = is_k ? Khi : Qhi;
        __nv_bfloat16* Lo = is_k ? Klo : Qlo;
        const int nb = is_k ? n0 - HID : n0;
#pragma unroll
        for (int mt = 0; mt < 4; ++mt)
#pragma unroll
            for (int nt = 0; nt < 8; ++nt) {
                const int row = m0 + wm * 64 + mt * 16 + cr;
                const int col = nb + wn * 64 + nt * 8 + cc;
                const float* c = acc[mt][nt];
#pragma unroll
                for (int h = 0; h < 2; ++h) {
                    float f0 = c[2 * h + 0], f1 = c[2 * h + 1];
                    if (!is_k) { f0 = fast_tanh(f0); f1 = fast_tanh(f1); }
                    __nv_bfloat16 h0 = __float2bfloat16(f0);
                    __nv_bfloat16 h1 = __float2bfloat16(f1);
                    __nv_bfloat16 l0 = __float2bfloat16(f0 - __bfloat162float(h0));
                    __nv_bfloat16 l1 = __float2bfloat16(f1 - __bfloat162float(h1));
                    const size_t o = (size_t)(row + 8 * h) * HID + col;
                    *(__nv_bfloat162*)(Ho + o) = __halves2bfloat162(h0, h1);
                    *(__nv_bfloat162*)(Lo + o) = __halves2bfloat162(l0, l1);
                }
            }
    }

    // ---- MODE 0: fused column-softmax partials over this CTA's 256x128 tile ----
    if (MODE == 0) {
        float* sred = (float*)smem;            // [4][128]
        float* scm  = (float*)(smem + 2048);   // [128]
        __syncthreads();
#pragma unroll
        for (int nt = 0; nt < 8; ++nt) {
#pragma unroll
            for (int p = 0; p < 2; ++p) {
                float m = acc[0][nt][p];
#pragma unroll
                for (int mt = 0; mt < 4; ++mt) {
                    m = fmaxf(m, acc[mt][nt][p]);
                    m = fmaxf(m, acc[mt][nt][p + 2]);
                }
                m = fmaxf(m, __shfl_xor_sync(0xffffffffu, m, 4));
                m = fmaxf(m, __shfl_xor_sync(0xffffffffu, m, 8));
                m = fmaxf(m, __shfl_xor_sync(0xffffffffu, m, 16));
                sred[wm * 128 + wn * 64 + nt * 8 + cc + p] = m;
            }
        }
        __syncthreads();
        if (tid < 128) {
            float m = fmaxf(fmaxf(sred[tid], sred[128 + tid]),
                            fmaxf(sred[256 + tid], sred[384 + tid]));
            scm[tid] = m;
        }
        __syncthreads();
#pragma unroll
        for (int nt = 0; nt < 8; ++nt) {
#pragma unroll
            for (int p = 0; p < 2; ++p) {
                const float m = scm[wn * 64 + nt * 8 + cc + p];
                float s = 0.f;
#pragma unroll
                for (int mt = 0; mt < 4; ++mt) {
                    s += __expf(acc[mt][nt][p] - m);
                    s += __expf(acc[mt][nt][p + 2] - m);
                }
                s += __shfl_xor_sync(0xffffffffu, s, 4);
                s += __shfl_xor_sync(0xffffffffu, s, 8);
                s += __shfl_xor_sync(0xffffffffu, s, 16);
                sred[wm * 128 + wn * 64 + nt * 8 + cc + p] = s;
            }
        }
        __syncthreads();
        if (tid < 128) {
            const int gi = blockIdx.y * SEQ + n0 + tid;
            g_pm[gi] = scm[tid];
            g_ps[gi] = sred[tid] + sred[128 + tid] + sred[256 + tid] + sred[384 + tid];
        }
    }
}

// ---------------- fp32 -> bf16 hi/lo split ----------------
__global__ void split_kernel(const float* __restrict__ src, __nv_bfloat16* __restrict__ hi,
                             __nv_bfloat16* __restrict__ lo, int n4)
{
    const int t = blockIdx.x * blockDim.x + threadIdx.x;
    if (t >= n4) return;
    float4 v = ((const float4*)src)[t];
    __nv_bfloat16 h0 = __float2bfloat16(v.x), h1 = __float2bfloat16(v.y);
    __nv_bfloat16 h2 = __float2bfloat16(v.z), h3 = __float2bfloat16(v.w);
    __nv_bfloat16 l0 = __float2bfloat16(v.x - __bfloat162float(h0));
    __nv_bfloat16 l1 = __float2bfloat16(v.y - __bfloat162float(h1));
    __nv_bfloat16 l2 = __float2bfloat16(v.z - __bfloat162float(h2));
    __nv_bfloat16 l3 = __float2bfloat16(v.w - __bfloat162float(h3));
    ((__nv_bfloat162*)hi)[2 * t + 0] = __halves2bfloat162(h0, h1);
    ((__nv_bfloat162*)hi)[2 * t + 1] = __halves2bfloat162(h2, h3);
    ((__nv_bfloat162*)lo)[2 * t + 0] = __halves2bfloat162(l0, l1);
    ((__nv_bfloat162*)lo)[2 * t + 1] = __halves2bfloat162(l2, l3);
}

// ---------------- softmax merge + normalize ----------------
__global__ void softmax_col_merge()
{
    const int j = blockIdx.x * blockDim.x + threadIdx.x;
    float m = -3.402823e38f;
#pragma unroll
    for (int c = 0; c < NCHUNK; c++) m = fmaxf(m, g_pm[c * SEQ + j]);
    float z = 0.f;
#pragma unroll
    for (int c = 0; c < NCHUNK; c++) z += g_ps[c * SEQ + j] * __expf(g_pm[c * SEQ + j] - m);
    g_cm[j] = m;
    g_cz[j] = 1.0f / z;
}

__global__ void softmax_normalize(const float* __restrict__ Sc, float* __restrict__ attn)
{
    const size_t t   = (size_t)blockIdx.x * blockDim.x + threadIdx.x;
    const size_t idx = t * 8;
    const int j = (int)(idx & (SEQ - 1));
    float4 x0 = *(const float4*)(Sc + idx);
    float4 x1 = *(const float4*)(Sc + idx + 4);
    float4 m0 = *(const float4*)(g_cm + j);
    float4 m1 = *(const float4*)(g_cm + j + 4);
    float4 z0 = *(const float4*)(g_cz + j);
    float4 z1 = *(const float4*)(g_cz + j + 4);
    float4 o0, o1;
    o0.x = __expf(x0.x - m0.x) * z0.x;
    o0.y = __expf(x0.y - m0.y) * z0.y;
    o0.z = __expf(x0.z - m0.z) * z0.z;
    o0.w = __expf(x0.w - m0.w) * z0.w;
    o1.x = __expf(x1.x - m1.x) * z1.x;
    o1.y = __expf(x1.y - m1.y) * z1.y;
    o1.z = __expf(x1.z - m1.z) * z1.z;
    o1.w = __expf(x1.w - m1.w) * z1.w;
    *(float4*)(attn + idx)     = o0;
    *(float4*)(attn + idx + 4) = o1;
}

// context = col_sum(attn) * enc_out; softmax column sums are exactly 1 -> copy.
__global__ void copy_context(const float* __restrict__ enc, float* __restrict__ ctx)
{
    const size_t t = (size_t)blockIdx.x * blockDim.x + threadIdx.x;
    ((float4*)ctx)[t] = ((const float4*)enc)[t];
}

// ============================================================================
extern "C" void kernel_launch(void* const* d_in, const int* in_sizes, int n_in,
                              void* d_out, int out_size)
{
    const float* enc = (const float*)d_in[0];
    const float* w1  = (const float*)d_in[1];
    const float* w2  = (const float*)d_in[2];
    float* out  = (float*)d_out;
    float* ctx  = out;
    float* attn = out + (size_t)SEQ * HID;

    __nv_bfloat16 *ehi, *elo, *wfhi, *wflo, *qhi, *qlo, *khi, *klo;
    float* sc;
    cudaGetSymbolAddress((void**)&ehi,  g_ehi);
    cudaGetSymbolAddress((void**)&elo,  g_elo);
    cudaGetSymbolAddress((void**)&wfhi, g_wfhi);
    cudaGetSymbolAddress((void**)&wflo, g_wflo);
    cudaGetSymbolAddress((void**)&qhi,  g_qhi);
    cudaGetSymbolAddress((void**)&qlo,  g_qlo);
    cudaGetSymbolAddress((void**)&khi,  g_khi);
    cudaGetSymbolAddress((void**)&klo,  g_klo);
    cudaGetSymbolAddress((void**)&sc,   g_sc);

    cudaFuncSetAttribute(gemm3_mma<0>, cudaFuncAttributeMaxDynamicSharedMemorySize, SMEM_TOT);
    cudaFuncSetAttribute(gemm3_mma<3>, cudaFuncAttributeMaxDynamicSharedMemorySize, SMEM_TOT);

    // 1) split inputs into bf16 hi/lo; weights concatenated as [w1; w2]
    split_kernel<<<(SEQ * HID / 4) / 256, 256>>>(enc, ehi, elo, SEQ * HID / 4);
    split_kernel<<<(HID * HID / 4) / 256, 256>>>(w1, wfhi, wflo, HID * HID / 4);
    split_kernel<<<(HID * HID / 4) / 256, 256>>>(w2, wfhi + HID * HID, wflo + HID * HID,
                                                 HID * HID / 4);

    // 2) fused: [q | k] = enc @ [w1; w2]^T, tanh on q half, bf16 hi/lo out
    gemm3_mma<3><<<dim3(2 * HID / 128, SEQ / 256), 256, SMEM_TOT>>>(
        ehi, elo, wfhi, wflo, nullptr, qhi, qlo, khi, klo, 2 * HID, HID);

    // 3) scores = q @ k^T (fp32) + fused column-softmax partials
    gemm3_mma<0><<<dim3(SEQ / 128, SEQ / 256), 256, SMEM_TOT>>>(
        qhi, qlo, khi, klo, sc, nullptr, nullptr, nullptr, nullptr, SEQ, HID);

    // 4) merge partials + normalize
    softmax_col_merge<<<SEQ / 256, 256>>>();
    softmax_normalize<<<((size_t)SEQ * SEQ / 8) / 256, 256>>>(sc, attn);

    // 5) context = enc_out
    copy_context<<<((size_t)SEQ * HID / 4) / 256, 256>>>(enc, ctx);
}